// round 3
// baseline (speedup 1.0000x reference)
#include <cuda_runtime.h>

#define NMAX 100000
#define FIN  128
#define FOUT 64
#define MT   256   // GEMM rows per block
#define KC   8     // GEMM k-chunk

// ---- scratch (static device globals; no allocations allowed) ----
__device__ int   g_deg[NMAX];
__device__ float g_dis[NMAX];
__device__ float g_z[(size_t)NMAX * FOUT];   // 25.6 MB, L2-resident
__device__ float g_Wc[FIN * FOUT];           // fused weight  W_gcn @ W_fc^T
__device__ float g_c[FOUT];                  // fused bias    W_fc @ b_gcn + b_fc

// ---------------------------------------------------------------------------
__global__ void k_zero_deg(int N) {
    int i = blockIdx.x * blockDim.x + threadIdx.x;
    if (i < N) g_deg[i] = 0;
}

__global__ void k_deg(const int* __restrict__ ecol, int E) {
    int i = blockIdx.x * blockDim.x + threadIdx.x;
    if (i < E) atomicAdd(&g_deg[ecol[i]], 1);   // compiles to RED (no return use)
}

__global__ void k_dis(int N) {
    int i = blockIdx.x * blockDim.x + threadIdx.x;
    if (i < N) g_dis[i] = rsqrtf((float)(g_deg[i] + 1));   // +1 self-loop
}

// Wc[k][o] = sum_m W_gcn[k][m] * W_fc[o][m];  c[o] = b_fc[o] + sum_m b_gcn[m]*W_fc[o][m]
__global__ void k_fuse_w(const float* __restrict__ Wg, const float* __restrict__ bg,
                         const float* __restrict__ Wf, const float* __restrict__ bf) {
    int o = threadIdx.x;          // 0..63
    int k = blockIdx.x;           // 0..128  (row 128 = bias)
    const float* wrow = (k < FIN) ? (Wg + (size_t)k * FIN) : bg;
    float s = 0.f;
    #pragma unroll 8
    for (int m = 0; m < FIN; m++) s += wrow[m] * Wf[(size_t)o * FIN + m];
    if (k < FIN) g_Wc[k * FOUT + o] = s;
    else         g_c[o] = s + bf[o];
}

// ---------------------------------------------------------------------------
// z = x @ Wc  (100000 x 64, K=128), fp32 via packed fma.rn.f32x2.
// Also initializes out[i] = c + dis[i]^2 * z[i]  (self-loop term + fused bias).
// Block: 256 threads, 256-row tile. Thread tile: 16 rows x 4 cols,
// rows kept as f32x2 pairs so accumulators are packed (2 FMA / instr).
__global__ void __launch_bounds__(256) k_gemm_init(const float* __restrict__ x,
                                                   float* __restrict__ out, int N) {
    __shared__ float Wcs[FIN][FOUT];          // 32 KB
    __shared__ float xs[KC][MT + 4];          // transposed x tile, ~8.3 KB

    int t = threadIdx.x;
    // load fused weight once
    {
        const float4* s = (const float4*)g_Wc;
        float4*       d = (float4*)&Wcs[0][0];
        #pragma unroll
        for (int i = 0; i < (FIN * FOUT / 4) / 256; i++) d[t + i * 256] = s[t + i * 256];
    }

    int row0 = blockIdx.x * MT;
    int tm = t >> 4;      // 0..15 -> rows row0 + tm*16 .. +15
    int tn = t & 15;      // cols tn*4 .. +3

    unsigned long long acc[8][4];             // 8 row-pairs x 4 cols, f32x2
    #pragma unroll
    for (int i = 0; i < 8; i++)
        #pragma unroll
        for (int j = 0; j < 4; j++) acc[i][j] = 0ULL;

    for (int kc = 0; kc < FIN; kc += KC) {
        __syncthreads();
        {   // each thread loads one row's 8-wide k-slab (32B, sector-aligned)
            int gr = row0 + t;
            float4 a = make_float4(0.f, 0.f, 0.f, 0.f), b = a;
            if (gr < N) {
                const float4* p = (const float4*)&x[(size_t)gr * FIN + kc];
                a = p[0]; b = p[1];
            }
            xs[0][t] = a.x; xs[1][t] = a.y; xs[2][t] = a.z; xs[3][t] = a.w;
            xs[4][t] = b.x; xs[5][t] = b.y; xs[6][t] = b.z; xs[7][t] = b.w;
        }
        __syncthreads();

        #pragma unroll
        for (int k = 0; k < KC; k++) {
            float4 bv = *(const float4*)&Wcs[kc + k][tn * 4];
            unsigned long long b2[4];
            asm("mov.b64 %0, {%1, %1};" : "=l"(b2[0]) : "f"(bv.x));
            asm("mov.b64 %0, {%1, %1};" : "=l"(b2[1]) : "f"(bv.y));
            asm("mov.b64 %0, {%1, %1};" : "=l"(b2[2]) : "f"(bv.z));
            asm("mov.b64 %0, {%1, %1};" : "=l"(b2[3]) : "f"(bv.w));

            const ulonglong2* ap = (const ulonglong2*)&xs[k][tm * 16];
            ulonglong2 p0 = ap[0], p1 = ap[1], p2 = ap[2], p3 = ap[3];
            unsigned long long av[8] = {p0.x, p0.y, p1.x, p1.y, p2.x, p2.y, p3.x, p3.y};

            #pragma unroll
            for (int i = 0; i < 8; i++)
                #pragma unroll
                for (int j = 0; j < 4; j++)
                    asm("fma.rn.f32x2 %0, %1, %2, %0;"
                        : "+l"(acc[i][j]) : "l"(av[i]), "l"(b2[j]));
        }
    }

    // epilogue: write z, and out = c + dis^2 * z
    float4 cb = *(const float4*)&g_c[tn * 4];
    #pragma unroll
    for (int i = 0; i < 8; i++) {
        int r = row0 + tm * 16 + 2 * i;
        float2 c0 = *(float2*)&acc[i][0];
        float2 c1 = *(float2*)&acc[i][1];
        float2 c2 = *(float2*)&acc[i][2];
        float2 c3 = *(float2*)&acc[i][3];
        if (r < N) {
            float d = g_dis[r]; float dd = d * d;
            float4 zv = make_float4(c0.x, c1.x, c2.x, c3.x);
            *(float4*)&g_z[(size_t)r * FOUT + tn * 4] = zv;
            *(float4*)&out[(size_t)r * FOUT + tn * 4] =
                make_float4(cb.x + dd * zv.x, cb.y + dd * zv.y,
                            cb.z + dd * zv.z, cb.w + dd * zv.w);
        }
        if (r + 1 < N) {
            float d = g_dis[r + 1]; float dd = d * d;
            float4 zv = make_float4(c0.y, c1.y, c2.y, c3.y);
            *(float4*)&g_z[(size_t)(r + 1) * FOUT + tn * 4] = zv;
            *(float4*)&out[(size_t)(r + 1) * FOUT + tn * 4] =
                make_float4(cb.x + dd * zv.x, cb.y + dd * zv.y,
                            cb.z + dd * zv.z, cb.w + dd * zv.w);
        }
    }
}

// ---------------------------------------------------------------------------
// Edge scatter: out[col] += dis[row]*dis[col] * z[row], 64 floats per edge.
// Half-warp (16 lanes) per edge -> 256B coalesced gather + 16x red.add.v4.
__global__ void __launch_bounds__(256) k_scatter(const int* __restrict__ erow,
                                                 const int* __restrict__ ecol,
                                                 float* __restrict__ out, int E) {
    int warp = (blockIdx.x * blockDim.x + threadIdx.x) >> 5;
    int lane = threadIdx.x & 31;
    int half = lane >> 4;
    int l    = lane & 15;
    int e = warp * 2 + half;
    if (e >= E) return;

    int r = __ldg(&erow[e]);
    int c = __ldg(&ecol[e]);
    float norm = g_dis[r] * g_dis[c];

    float4 v = *(const float4*)&g_z[(size_t)r * FOUT + l * 4];
    float* dst = &out[(size_t)c * FOUT + l * 4];
    asm volatile("red.global.add.v4.f32 [%0], {%1, %2, %3, %4};"
                 :: "l"(dst), "f"(v.x * norm), "f"(v.y * norm),
                    "f"(v.z * norm), "f"(v.w * norm)
                 : "memory");
}

// ---------------------------------------------------------------------------
extern "C" void kernel_launch(void* const* d_in, const int* in_sizes, int n_in,
                              void* d_out, int out_size) {
    const float* x  = (const float*)d_in[0];
    const int*   ei = (const int*)d_in[1];
    const float* Wg = (const float*)d_in[2];
    const float* bg = (const float*)d_in[3];
    const float* Wf = (const float*)d_in[4];
    const float* bf = (const float*)d_in[5];
    float* out = (float*)d_out;

    int N = in_sizes[0] / FIN;
    int E = in_sizes[1] / 2;
    const int* erow = ei;        // sources
    const int* ecol = ei + E;    // targets (aggregation index)

    k_zero_deg<<<(N + 255) / 256, 256>>>(N);
    k_deg<<<(E + 255) / 256, 256>>>(ecol, E);
    k_dis<<<(N + 255) / 256, 256>>>(N);
    k_fuse_w<<<FIN + 1, FOUT>>>(Wg, bg, Wf, bf);
    k_gemm_init<<<(N + MT - 1) / MT, 256>>>(x, out, N);
    k_scatter<<<(E + 15) / 16, 256>>>(erow, ecol, out, E);
}

// round 4
// speedup vs baseline: 1.0765x; 1.0765x over previous
#include <cuda_runtime.h>
#include <cuda_fp16.h>

#define NMAX 100000
#define FIN  128
#define FOUT 64
#define MT   256   // GEMM rows per block
#define KC   8     // GEMM k-chunk

// ---- scratch (static device globals; no allocations allowed) ----
__device__ int    g_deg[NMAX];
__device__ float  g_dis[NMAX];
__device__ __half g_zs[(size_t)NMAX * FOUT];   // fp16 pre-scaled messages dis[r]*z[r], 12.8 MB
__device__ float  g_Wc[FIN * FOUT];            // fused weight  W_gcn @ W_fc^T
__device__ float  g_c[FOUT];                   // fused bias    W_fc @ b_gcn + b_fc

// ---------------------------------------------------------------------------
__global__ void k_zero_deg(int N) {
    int i = blockIdx.x * blockDim.x + threadIdx.x;
    if (i < N) g_deg[i] = 0;
}

__global__ void k_deg(const int* __restrict__ ecol, int E) {
    int i = blockIdx.x * blockDim.x + threadIdx.x;
    if (i < E) atomicAdd(&g_deg[ecol[i]], 1);   // compiles to RED (no return use)
}

__global__ void k_dis(int N) {
    int i = blockIdx.x * blockDim.x + threadIdx.x;
    if (i < N) g_dis[i] = rsqrtf((float)(g_deg[i] + 1));   // +1 self-loop
}

// Wc[k][o] = sum_m W_gcn[k][m] * W_fc[o][m];  c[o] = b_fc[o] + sum_m b_gcn[m]*W_fc[o][m]
// Coalesced: stage W_fc transposed in smem (pad 65 -> conflict-free LDS).
__global__ void __launch_bounds__(256) k_fuse_w(const float* __restrict__ Wg,
                                                const float* __restrict__ bg,
                                                const float* __restrict__ Wf,
                                                const float* __restrict__ bf) {
    __shared__ float Wfs[FIN][FOUT + 1];      // [m][o], ~33 KB
    int t = threadIdx.x;
    #pragma unroll
    for (int i = 0; i < (FOUT * FIN) / 256; i++) {
        int idx = t + i * 256;                // coalesced read of Wf[o][m]
        int o = idx >> 7, m = idx & 127;
        Wfs[m][o] = Wf[idx];
    }
    __syncthreads();

    int gid = blockIdx.x * 256 + t;           // (FIN+1)*FOUT = 8256 outputs
    int k = gid >> 6;                         // 0..128 (128 = bias row)
    int o = gid & 63;
    if (k > FIN) return;
    const float* wrow = (k < FIN) ? (Wg + (size_t)k * FIN) : bg;
    float s = 0.f;
    #pragma unroll 16
    for (int m = 0; m < FIN; m++) s += __ldg(&wrow[m]) * Wfs[m][o];  // bcast LDG + LDS
    if (k < FIN) g_Wc[k * FOUT + o] = s;
    else         g_c[o] = s + bf[o];
}

// ---------------------------------------------------------------------------
// z = x @ Wc  (100000 x 64, K=128), fp32 via packed fma.rn.f32x2.
// Epilogue: out[i] = c + dis[i]^2 * z[i]  (self-loop, full fp32)
//           zs[i]  = fp16(dis[i] * z[i])  (pre-scaled scatter message)
__global__ void __launch_bounds__(256) k_gemm_init(const float* __restrict__ x,
                                                   float* __restrict__ out, int N) {
    __shared__ float Wcs[FIN][FOUT];          // 32 KB
    __shared__ float xs[KC][MT + 4];          // transposed x tile

    int t = threadIdx.x;
    {
        const float4* s = (const float4*)g_Wc;
        float4*       d = (float4*)&Wcs[0][0];
        #pragma unroll
        for (int i = 0; i < (FIN * FOUT / 4) / 256; i++) d[t + i * 256] = s[t + i * 256];
    }

    int row0 = blockIdx.x * MT;
    int tm = t >> 4;      // 0..15 -> rows row0 + tm*16 .. +15
    int tn = t & 15;      // cols tn*4 .. +3

    unsigned long long acc[8][4];             // 8 row-pairs x 4 cols, f32x2
    #pragma unroll
    for (int i = 0; i < 8; i++)
        #pragma unroll
        for (int j = 0; j < 4; j++) acc[i][j] = 0ULL;

    for (int kc = 0; kc < FIN; kc += KC) {
        __syncthreads();
        {
            int gr = row0 + t;
            float4 a = make_float4(0.f, 0.f, 0.f, 0.f), b = a;
            if (gr < N) {
                const float4* p = (const float4*)&x[(size_t)gr * FIN + kc];
                a = p[0]; b = p[1];
            }
            xs[0][t] = a.x; xs[1][t] = a.y; xs[2][t] = a.z; xs[3][t] = a.w;
            xs[4][t] = b.x; xs[5][t] = b.y; xs[6][t] = b.z; xs[7][t] = b.w;
        }
        __syncthreads();

        #pragma unroll
        for (int k = 0; k < KC; k++) {
            float4 bv = *(const float4*)&Wcs[kc + k][tn * 4];
            unsigned long long b2[4];
            asm("mov.b64 %0, {%1, %1};" : "=l"(b2[0]) : "f"(bv.x));
            asm("mov.b64 %0, {%1, %1};" : "=l"(b2[1]) : "f"(bv.y));
            asm("mov.b64 %0, {%1, %1};" : "=l"(b2[2]) : "f"(bv.z));
            asm("mov.b64 %0, {%1, %1};" : "=l"(b2[3]) : "f"(bv.w));

            const ulonglong2* ap = (const ulonglong2*)&xs[k][tm * 16];
            ulonglong2 p0 = ap[0], p1 = ap[1], p2 = ap[2], p3 = ap[3];
            unsigned long long av[8] = {p0.x, p0.y, p1.x, p1.y, p2.x, p2.y, p3.x, p3.y};

            #pragma unroll
            for (int i = 0; i < 8; i++)
                #pragma unroll
                for (int j = 0; j < 4; j++)
                    asm("fma.rn.f32x2 %0, %1, %2, %0;"
                        : "+l"(acc[i][j]) : "l"(av[i]), "l"(b2[j]));
        }
    }

    float4 cb = *(const float4*)&g_c[tn * 4];
    #pragma unroll
    for (int i = 0; i < 8; i++) {
        int r = row0 + tm * 16 + 2 * i;
        float2 c0 = *(float2*)&acc[i][0];
        float2 c1 = *(float2*)&acc[i][1];
        float2 c2 = *(float2*)&acc[i][2];
        float2 c3 = *(float2*)&acc[i][3];
        #pragma unroll
        for (int s = 0; s < 2; s++) {
            int rr = r + s;
            if (rr >= N) break;
            float4 zv = s ? make_float4(c0.y, c1.y, c2.y, c3.y)
                          : make_float4(c0.x, c1.x, c2.x, c3.x);
            float d = g_dis[rr]; float dd = d * d;
            *(float4*)&out[(size_t)rr * FOUT + tn * 4] =
                make_float4(cb.x + dd * zv.x, cb.y + dd * zv.y,
                            cb.z + dd * zv.z, cb.w + dd * zv.w);
            __half2 h0 = __float22half2_rn(make_float2(d * zv.x, d * zv.y));
            __half2 h1 = __float22half2_rn(make_float2(d * zv.z, d * zv.w));
            uint2 pk;
            pk.x = *(unsigned int*)&h0;
            pk.y = *(unsigned int*)&h1;
            *(uint2*)&g_zs[(size_t)rr * FOUT + tn * 4] = pk;   // 8B aligned
        }
    }
}

// ---------------------------------------------------------------------------
// Edge scatter: out[col] += dis[col] * zs[row], 64 halves per edge.
// Half-warp (16 lanes) per edge -> 128B coalesced fp16 gather + 16x red.add.v4.f32.
__global__ void __launch_bounds__(256) k_scatter(const int* __restrict__ erow,
                                                 const int* __restrict__ ecol,
                                                 float* __restrict__ out, int E) {
    int warp = (blockIdx.x * blockDim.x + threadIdx.x) >> 5;
    int lane = threadIdx.x & 31;
    int half = lane >> 4;
    int l    = lane & 15;
    int e = warp * 2 + half;
    if (e >= E) return;

    int r = __ldg(&erow[e]);
    int c = __ldg(&ecol[e]);
    float dc = g_dis[c];

    uint2 u = *(const uint2*)&g_zs[(size_t)r * FOUT + l * 4];   // 4 halves
    __half2 h0 = *reinterpret_cast<__half2*>(&u.x);
    __half2 h1 = *reinterpret_cast<__half2*>(&u.y);
    float2 f0 = __half22float2(h0);
    float2 f1 = __half22float2(h1);

    float* dst = &out[(size_t)c * FOUT + l * 4];
    asm volatile("red.global.add.v4.f32 [%0], {%1, %2, %3, %4};"
                 :: "l"(dst), "f"(f0.x * dc), "f"(f0.y * dc),
                    "f"(f1.x * dc), "f"(f1.y * dc)
                 : "memory");
}

// ---------------------------------------------------------------------------
extern "C" void kernel_launch(void* const* d_in, const int* in_sizes, int n_in,
                              void* d_out, int out_size) {
    const float* x  = (const float*)d_in[0];
    const int*   ei = (const int*)d_in[1];
    const float* Wg = (const float*)d_in[2];
    const float* bg = (const float*)d_in[3];
    const float* Wf = (const float*)d_in[4];
    const float* bf = (const float*)d_in[5];
    float* out = (float*)d_out;

    int N = in_sizes[0] / FIN;
    int E = in_sizes[1] / 2;
    const int* erow = ei;        // sources
    const int* ecol = ei + E;    // targets (aggregation index)

    k_zero_deg<<<(N + 255) / 256, 256>>>(N);
    k_deg<<<(E + 255) / 256, 256>>>(ecol, E);
    k_dis<<<(N + 255) / 256, 256>>>(N);
    k_fuse_w<<<((FIN + 1) * FOUT + 255) / 256, 256>>>(Wg, bg, Wf, bf);
    k_gemm_init<<<(N + MT - 1) / MT, 256>>>(x, out, N);
    k_scatter<<<(E + 15) / 16, 256>>>(erow, ecol, out, E);
}

// round 5
// speedup vs baseline: 1.2587x; 1.1693x over previous
#include <cuda_runtime.h>
#include <cuda_fp16.h>

#define NMAX 100000
#define EMAX 1600000
#define FIN  128
#define FOUT 64
#define MT   256   // GEMM rows per block
#define KC   8     // GEMM k-chunk
#define SCAN_BLOCKS ((NMAX + 255) / 256)   // 391

// ---- scratch (static device globals; no allocations allowed) ----
__device__ int    g_deg[NMAX];
__device__ float  g_dis[NMAX];
__device__ __align__(128) __half g_zs[(size_t)NMAX * FOUT]; // fp16 dis[r]*z[r], 12.8 MB
__device__ float  g_Wc[FIN * FOUT];            // fused weight  W_gcn @ W_fc^T
__device__ float  g_c[FOUT];                   // fused bias    W_fc @ b_gcn + b_fc
// CSR scratch
__device__ int    g_off[NMAX + 1];
__device__ int    g_cur[NMAX];
__device__ int    g_bsum[SCAN_BLOCKS];
__device__ int    g_eidx[EMAX];                // source node per CSR slot

// ---------------------------------------------------------------------------
__global__ void k_zero_deg(int N) {
    int i = blockIdx.x * blockDim.x + threadIdx.x;
    if (i < N) g_deg[i] = 0;
}

__global__ void k_deg(const int* __restrict__ ecol, int E) {
    int i = blockIdx.x * blockDim.x + threadIdx.x;
    if (i < E) atomicAdd(&g_deg[ecol[i]], 1);   // RED
}

__global__ void k_dis(int N) {
    int i = blockIdx.x * blockDim.x + threadIdx.x;
    if (i < N) g_dis[i] = rsqrtf((float)(g_deg[i] + 1));   // +1 self-loop
}

// ---------------------------------------------------------------------------
// Wc[k][o] = sum_m W_gcn[k][m] * W_fc[o][m];  c[o] = b_fc[o] + W_fc @ b_gcn
// One warp per output: coalesced loads + shfl reduce. 8256 warps.
__global__ void __launch_bounds__(256) k_fuse_w(const float* __restrict__ Wg,
                                                const float* __restrict__ bg,
                                                const float* __restrict__ Wf,
                                                const float* __restrict__ bf) {
    int w = (blockIdx.x * 256 + threadIdx.x) >> 5;
    int lane = threadIdx.x & 31;
    if (w >= (FIN + 1) * FOUT) return;
    int k = w >> 6;           // 0..128 (128 = bias row)
    int o = w & 63;
    const float* wrow = (k < FIN) ? (Wg + (size_t)k * FIN) : bg;
    float s = 0.f;
    #pragma unroll
    for (int m = lane; m < FIN; m += 32) s += wrow[m] * Wf[(size_t)o * FIN + m];
    #pragma unroll
    for (int d = 16; d; d >>= 1) s += __shfl_xor_sync(0xffffffff, s, d);
    if (lane == 0) {
        if (k < FIN) g_Wc[k * FOUT + o] = s;
        else         g_c[o] = s + bf[o];
    }
}

// ---------------------------------------------------------------------------
// CSR build: exclusive scan of g_deg -> g_off / g_cur, then slot fill.
__global__ void k_scan1(int N) {
    int i = blockIdx.x * 256 + threadIdx.x;
    int lane = threadIdx.x & 31, wid = threadIdx.x >> 5;
    int orig = (i < N) ? g_deg[i] : 0;
    int v = orig;
    #pragma unroll
    for (int d = 1; d < 32; d <<= 1) {
        int n = __shfl_up_sync(0xffffffff, v, d);
        if (lane >= d) v += n;
    }
    __shared__ int ws[8];
    if (lane == 31) ws[wid] = v;
    __syncthreads();
    if (threadIdx.x == 0) {
        int s = 0;
        #pragma unroll
        for (int q = 0; q < 8; q++) { int t = ws[q]; ws[q] = s; s += t; }
        g_bsum[blockIdx.x] = s;
    }
    __syncthreads();
    if (i < N) g_off[i] = v - orig + ws[wid];   // block-local exclusive
}

__global__ void k_scan2(int nb) {               // single block, 512 threads
    __shared__ int s[512];
    int t = threadIdx.x;
    int orig = (t < nb) ? g_bsum[t] : 0;
    s[t] = orig;
    __syncthreads();
    for (int d = 1; d < 512; d <<= 1) {
        int add = (t >= d) ? s[t - d] : 0;
        __syncthreads();
        s[t] += add;
        __syncthreads();
    }
    if (t < nb) g_bsum[t] = s[t] - orig;        // exclusive
}

__global__ void k_scan3(int N, int E) {
    int i = blockIdx.x * 256 + threadIdx.x;
    if (i < N) {
        int off = g_off[i] + g_bsum[blockIdx.x];
        g_off[i] = off;
        g_cur[i] = off;
    }
    if (i == 0) g_off[N] = E;
}

__global__ void k_fill(const int* __restrict__ erow, const int* __restrict__ ecol, int E) {
    int i = blockIdx.x * blockDim.x + threadIdx.x;
    if (i < E) {
        int c = ecol[i];
        int slot = atomicAdd(&g_cur[c], 1);
        g_eidx[slot] = erow[i];
    }
}

// ---------------------------------------------------------------------------
// z = x @ Wc  (100000 x 64, K=128), fp32 via packed fma.rn.f32x2.
// Epilogue: out[i] = c + dis[i]^2 * z[i]; zs[i] = fp16(dis[i]*z[i]).
__global__ void __launch_bounds__(256) k_gemm_init(const float* __restrict__ x,
                                                   float* __restrict__ out, int N) {
    __shared__ float Wcs[FIN][FOUT];
    __shared__ float xs[KC][MT + 4];

    int t = threadIdx.x;
    {
        const float4* s = (const float4*)g_Wc;
        float4*       d = (float4*)&Wcs[0][0];
        #pragma unroll
        for (int i = 0; i < (FIN * FOUT / 4) / 256; i++) d[t + i * 256] = s[t + i * 256];
    }

    int row0 = blockIdx.x * MT;
    int tm = t >> 4;
    int tn = t & 15;

    unsigned long long acc[8][4];
    #pragma unroll
    for (int i = 0; i < 8; i++)
        #pragma unroll
        for (int j = 0; j < 4; j++) acc[i][j] = 0ULL;

    for (int kc = 0; kc < FIN; kc += KC) {
        __syncthreads();
        {
            int gr = row0 + t;
            float4 a = make_float4(0.f, 0.f, 0.f, 0.f), b = a;
            if (gr < N) {
                const float4* p = (const float4*)&x[(size_t)gr * FIN + kc];
                a = p[0]; b = p[1];
            }
            xs[0][t] = a.x; xs[1][t] = a.y; xs[2][t] = a.z; xs[3][t] = a.w;
            xs[4][t] = b.x; xs[5][t] = b.y; xs[6][t] = b.z; xs[7][t] = b.w;
        }
        __syncthreads();

        #pragma unroll
        for (int k = 0; k < KC; k++) {
            float4 bv = *(const float4*)&Wcs[kc + k][tn * 4];
            unsigned long long b2[4];
            asm("mov.b64 %0, {%1, %1};" : "=l"(b2[0]) : "f"(bv.x));
            asm("mov.b64 %0, {%1, %1};" : "=l"(b2[1]) : "f"(bv.y));
            asm("mov.b64 %0, {%1, %1};" : "=l"(b2[2]) : "f"(bv.z));
            asm("mov.b64 %0, {%1, %1};" : "=l"(b2[3]) : "f"(bv.w));

            const ulonglong2* ap = (const ulonglong2*)&xs[k][tm * 16];
            ulonglong2 p0 = ap[0], p1 = ap[1], p2 = ap[2], p3 = ap[3];
            unsigned long long av[8] = {p0.x, p0.y, p1.x, p1.y, p2.x, p2.y, p3.x, p3.y};

            #pragma unroll
            for (int i = 0; i < 8; i++)
                #pragma unroll
                for (int j = 0; j < 4; j++)
                    asm("fma.rn.f32x2 %0, %1, %2, %0;"
                        : "+l"(acc[i][j]) : "l"(av[i]), "l"(b2[j]));
        }
    }

    float4 cb = *(const float4*)&g_c[tn * 4];
    #pragma unroll
    for (int i = 0; i < 8; i++) {
        int r = row0 + tm * 16 + 2 * i;
        float2 c0 = *(float2*)&acc[i][0];
        float2 c1 = *(float2*)&acc[i][1];
        float2 c2 = *(float2*)&acc[i][2];
        float2 c3 = *(float2*)&acc[i][3];
        #pragma unroll
        for (int s = 0; s < 2; s++) {
            int rr = r + s;
            if (rr >= N) break;
            float4 zv = s ? make_float4(c0.y, c1.y, c2.y, c3.y)
                          : make_float4(c0.x, c1.x, c2.x, c3.x);
            float d = g_dis[rr]; float dd = d * d;
            *(float4*)&out[(size_t)rr * FOUT + tn * 4] =
                make_float4(cb.x + dd * zv.x, cb.y + dd * zv.y,
                            cb.z + dd * zv.z, cb.w + dd * zv.w);
            __half2 h0 = __float22half2_rn(make_float2(d * zv.x, d * zv.y));
            __half2 h1 = __float22half2_rn(make_float2(d * zv.z, d * zv.w));
            uint2 pk;
            pk.x = *(unsigned int*)&h0;
            pk.y = *(unsigned int*)&h1;
            *(uint2*)&g_zs[(size_t)rr * FOUT + tn * 4] = pk;
        }
    }
}

// ---------------------------------------------------------------------------
// Aggregation: one warp per target node. Lanes hold 2 dims each (64 dims / 32).
// Gather 128B fp16 rows, fp32 accumulate, dis[c] applied once, single RMW.
__global__ void __launch_bounds__(256) k_aggr(float* __restrict__ out, int N) {
    int w = (blockIdx.x * 256 + threadIdx.x) >> 5;
    int lane = threadIdx.x & 31;
    if (w >= N) return;
    int c = w;
    int off0 = g_off[c], off1 = g_off[c + 1];

    float2 acc = make_float2(0.f, 0.f);
    for (int base = off0; base < off1; base += 32) {
        int cnt = min(32, off1 - base);
        int myE = base + lane;
        int rl = (lane < cnt) ? __ldg(&g_eidx[myE]) : 0;
        int j = 0;
        for (; j + 4 <= cnt; j += 4) {
            int r0 = __shfl_sync(0xffffffff, rl, j);
            int r1 = __shfl_sync(0xffffffff, rl, j + 1);
            int r2 = __shfl_sync(0xffffffff, rl, j + 2);
            int r3 = __shfl_sync(0xffffffff, rl, j + 3);
            unsigned u0 = *(const unsigned*)&g_zs[(size_t)r0 * FOUT + lane * 2];
            unsigned u1 = *(const unsigned*)&g_zs[(size_t)r1 * FOUT + lane * 2];
            unsigned u2 = *(const unsigned*)&g_zs[(size_t)r2 * FOUT + lane * 2];
            unsigned u3 = *(const unsigned*)&g_zs[(size_t)r3 * FOUT + lane * 2];
            float2 f0 = __half22float2(*reinterpret_cast<__half2*>(&u0));
            float2 f1 = __half22float2(*reinterpret_cast<__half2*>(&u1));
            float2 f2 = __half22float2(*reinterpret_cast<__half2*>(&u2));
            float2 f3 = __half22float2(*reinterpret_cast<__half2*>(&u3));
            acc.x += f0.x + f1.x + f2.x + f3.x;
            acc.y += f0.y + f1.y + f2.y + f3.y;
        }
        for (; j < cnt; j++) {
            int r = __shfl_sync(0xffffffff, rl, j);
            unsigned u = *(const unsigned*)&g_zs[(size_t)r * FOUT + lane * 2];
            float2 f = __half22float2(*reinterpret_cast<__half2*>(&u));
            acc.x += f.x; acc.y += f.y;
        }
    }
    if (off1 > off0) {
        float dc = g_dis[c];
        float2* o = (float2*)&out[(size_t)c * FOUT + lane * 2];
        float2 cur = *o;
        cur.x += dc * acc.x;
        cur.y += dc * acc.y;
        *o = cur;
    }
}

// ---------------------------------------------------------------------------
extern "C" void kernel_launch(void* const* d_in, const int* in_sizes, int n_in,
                              void* d_out, int out_size) {
    const float* x  = (const float*)d_in[0];
    const int*   ei = (const int*)d_in[1];
    const float* Wg = (const float*)d_in[2];
    const float* bg = (const float*)d_in[3];
    const float* Wf = (const float*)d_in[4];
    const float* bf = (const float*)d_in[5];
    float* out = (float*)d_out;

    int N = in_sizes[0] / FIN;
    int E = in_sizes[1] / 2;
    const int* erow = ei;        // sources
    const int* ecol = ei + E;    // targets (aggregation index)

    int nb = (N + 255) / 256;    // == SCAN_BLOCKS for N=100000

    k_zero_deg<<<nb, 256>>>(N);
    k_deg<<<(E + 255) / 256, 256>>>(ecol, E);
    k_dis<<<nb, 256>>>(N);
    k_fuse_w<<<((FIN + 1) * FOUT * 32 + 255) / 256, 256>>>(Wg, bg, Wf, bf);
    k_scan1<<<nb, 256>>>(N);
    k_scan2<<<1, 512>>>(nb);
    k_scan3<<<nb, 256>>>(N, E);
    k_fill<<<(E + 255) / 256, 256>>>(erow, ecol, E);
    k_gemm_init<<<(N + MT - 1) / MT, 256>>>(x, out, N);
    k_aggr<<<(N * 32 + 255) / 256, 256>>>(out, N);
}